// round 12
// baseline (speedup 1.0000x reference)
#include <cuda_runtime.h>
#include <math.h>
#include <float.h>

#define B_   128
#define H_   512
#define E_   256
#define ND_  128
#define V_   5000
#define K0_  384      // E_ + ND_

typedef unsigned long long u64;

// ---------------- persistent device state ----------------
__device__ __align__(16) float g_h0T[2][H_ * B_];   // [k][b], ping-pong
__device__ __align__(16) float g_h1T[2][H_ * B_];
__device__ __align__(16) float g_c0[H_ * B_];       // cell state [j][b]
__device__ __align__(16) float g_c1[H_ * B_];
__device__ __align__(16) float g_xnT[ND_ * B_];     // noise transposed [k][b]
__device__ __align__(16) float g_cval[125 * B_];    // [p][b]
__device__ int   g_cidx[125 * B_];

__device__ __forceinline__ float sigmf(float x) { return 1.0f / (1.0f + expf(-x)); }

__device__ __forceinline__ u64 pack2(float lo, float hi) {
    u64 r; asm("mov.b64 %0,{%1,%2};" : "=l"(r) : "f"(lo), "f"(hi)); return r;
}
__device__ __forceinline__ void fma2(u64& d, u64 x, u64 w) {
    asm("fma.rn.f32x2 %0,%1,%2,%0;" : "+l"(d) : "l"(x), "l"(w));
}
__device__ __forceinline__ void unpack2(u64 a, float& x, float& y) {
    asm("mov.b64 {%0,%1},%2;" : "=f"(x), "=f"(y) : "l"(a));
}
__device__ __forceinline__ float hsum2(u64 a) {
    float x, y; unpack2(a, x, y); return x + y;
}
__device__ __forceinline__ void cpa16(unsigned s, const void* g) {
    asm volatile("cp.async.cg.shared.global [%0], [%1], 16;" :: "r"(s), "l"(g));
}
__device__ __forceinline__ void cpcommit() { asm volatile("cp.async.commit_group;"); }
__device__ __forceinline__ void cpwait1()  { asm volatile("cp.async.wait_group 1;"); }

// ================= init =================
__global__ void k_init(const float* __restrict__ noise) {
    int i = blockIdx.x * 256 + threadIdx.x;
    if (i < H_ * B_) {
        g_h0T[0][i] = 0.f; g_h1T[0][i] = 0.f;
        g_c0[i] = 0.f;     g_c1[i] = 0.f;
    }
    if (i < ND_ * B_) {
        int k = i >> 7, b = i & 127;
        g_xnT[k * B_ + b] = noise[b * ND_ + k];
    }
}

// ================= LSTM kernels =================
// grid 128, block 256 = 8 warps: rg = wid>>1 -> j = jbase+rg, bg = wid&1 -> 64-batch half.
// Lane owns 2 b. acc[gate][b] u64 = (even-k sum, odd-k sum).
// Weights cp.async-pipelined in 64-k chunks, 3 smem stages, natural (w_k,w_k+1) pairs.
template<int LAYER>
__global__ void __launch_bounds__(256) k_lstm(
    const float* __restrict__ emb,
    const float* __restrict__ Wih, const float* __restrict__ Whh,
    const float* __restrict__ bih, const float* __restrict__ bhh, int t)
{
    constexpr int KIH = (LAYER == 0) ? K0_ : H_;
    constexpr int CIH = KIH / 64;          // 6 or 8
    constexpr int NC  = CIH + 8;           // 14 or 16

    __shared__ __align__(16) float wsm[3][16][64];   // 12KB
    __shared__ int s_tok[B_];

    const int tid = threadIdx.x, bid = blockIdx.x;
    const int lane = tid & 31, wid = tid >> 5;
    const int rg = wid >> 1, bg = wid & 1;
    const int b2 = bg * 64 + lane * 2;
    const int jbase = bid * 4;
    const int j = jbase + rg;

    // ---- fused token reduce (layer 0) ----
    if (LAYER == 0) {
        if (tid < B_) {
            int tok = 1;
            if (t > 0) {
                float bv = -FLT_MAX; int bi = 0x7fffffff;
                #pragma unroll 5
                for (int p = 0; p < 125; p++) {
                    float v = g_cval[p * B_ + tid];
                    int  ix = g_cidx[p * B_ + tid];
                    if (v > bv || (v == bv && ix < bi)) { bv = v; bi = ix; }
                }
                tok = bi;
            }
            s_tok[tid] = tok;
        }
        __syncthreads();
    }

    // staging role: row = tid>>4 (0..15), 16B unit q = tid&15
    const int srow = tid >> 4, sq = (tid & 15) * 4;
    const int sg = srow >> 2, sj = srow & 3;
    const float* rowIH = Wih + (size_t)(sg * H_ + jbase + sj) * KIH + sq;
    const float* rowHH = Whh + (size_t)(sg * H_ + jbase + sj) * H_  + sq;
    unsigned smb[3];
    #pragma unroll
    for (int s = 0; s < 3; s++)
        smb[s] = (unsigned)__cvta_generic_to_shared(&wsm[s][srow][sq]);

    const float* hprev = (LAYER == 0) ? g_h0T[t & 1] : g_h1T[t & 1];
    const float* xinL1 = g_h0T[(t + 1) & 1];
    const float* e0 = emb + (size_t)((LAYER == 0) ? s_tok[b2]     : 0) * E_;
    const float* e1 = emb + (size_t)((LAYER == 0) ? s_tok[b2 + 1] : 0) * E_;

    u64 acc[4][2];
    #pragma unroll
    for (int g = 0; g < 4; g++) { acc[g][0] = 0ull; acc[g][1] = 0ull; }

    // prologue: stage chunks 0,1
    cpa16(smb[0], (0 < CIH) ? rowIH : rowHH);
    cpcommit();
    cpa16(smb[1], (1 < CIH) ? rowIH + 64 : rowHH + (1 - CIH) * 64);
    cpcommit();

    #pragma unroll 1
    for (int c = 0; c < NC; c++) {
        cpwait1();
        __syncthreads();
        const int st = c - (c / 3) * 3;

        if (LAYER == 0 && c < 4) {
            // x from embedding rows
            const int kb = c * 64;
            #pragma unroll 4
            for (int kc = 0; kc < 64; kc += 4) {
                float4 f0 = *(const float4*)(e0 + kb + kc);
                float4 f1 = *(const float4*)(e1 + kb + kc);
                u64 p0 = pack2(f0.x, f0.y), p1 = pack2(f1.x, f1.y);
                u64 p2 = pack2(f0.z, f0.w), p3 = pack2(f1.z, f1.w);
                #pragma unroll
                for (int g = 0; g < 4; g++) {
                    ulonglong2 w = *(const ulonglong2*)&wsm[st][g * 4 + rg][kc];
                    fma2(acc[g][0], p0, w.x); fma2(acc[g][1], p1, w.x);
                    fma2(acc[g][0], p2, w.y); fma2(acc[g][1], p3, w.y);
                }
            }
        } else {
            const float* xk;
            if (LAYER == 0) xk = (c < 6) ? g_xnT + (size_t)(c - 4) * 64 * B_
                                         : hprev + (size_t)(c - 6) * 64 * B_;
            else            xk = (c < 8) ? xinL1 + (size_t)c * 64 * B_
                                         : hprev + (size_t)(c - 8) * 64 * B_;
            const float* xp0 = xk + b2;
            #pragma unroll 4
            for (int kc = 0; kc < 64; kc += 4) {
                const float* xp = xp0 + (size_t)kc * B_;
                float2 a0 = *(const float2*)(xp);
                float2 a1 = *(const float2*)(xp + B_);
                float2 a2 = *(const float2*)(xp + 2 * B_);
                float2 a3 = *(const float2*)(xp + 3 * B_);
                u64 p0 = pack2(a0.x, a1.x), p1 = pack2(a0.y, a1.y);
                u64 p2 = pack2(a2.x, a3.x), p3 = pack2(a2.y, a3.y);
                #pragma unroll
                for (int g = 0; g < 4; g++) {
                    ulonglong2 w = *(const ulonglong2*)&wsm[st][g * 4 + rg][kc];
                    fma2(acc[g][0], p0, w.x); fma2(acc[g][1], p1, w.x);
                    fma2(acc[g][0], p2, w.y); fma2(acc[g][1], p3, w.y);
                }
            }
        }

        if (c + 2 < NC) {
            int cn = c + 2;
            const float* src = (cn < CIH) ? rowIH + cn * 64
                                          : rowHH + (cn - CIH) * 64;
            cpa16(smb[cn - (cn / 3) * 3], src);
        }
        cpcommit();
    }

    // ---- warp-local epilogue: j, batch b2..b2+1 ----
    {
        float* cst  = (LAYER == 0) ? g_c0 : g_c1;
        float* h_wr = (LAYER == 0) ? g_h0T[(t + 1) & 1] : g_h1T[(t + 1) & 1];
        float gx[4], gy[4];
        #pragma unroll
        for (int g = 0; g < 4; g++) {
            float bs = bih[g * H_ + j] + bhh[g * H_ + j];
            gx[g] = hsum2(acc[g][0]) + bs;
            gy[g] = hsum2(acc[g][1]) + bs;
        }
        float2 cold = *(float2*)&cst[j * B_ + b2];
        float i0 = sigmf(gx[0]), f0 = sigmf(gx[1]), g0 = tanhf(gx[2]), o0 = sigmf(gx[3]);
        float i1 = sigmf(gy[0]), f1 = sigmf(gy[1]), g1 = tanhf(gy[2]), o1 = sigmf(gy[3]);
        float c0n = f0 * cold.x + i0 * g0;
        float c1n = f1 * cold.y + i1 * g1;
        *(float2*)&cst[j * B_ + b2]  = make_float2(c0n, c1n);
        *(float2*)&h_wr[j * B_ + b2] = make_float2(o0 * tanhf(c0n), o1 * tanhf(c1n));
    }
}

// ================= logits + partial argmax =================
// grid 125, block 256 = 8 warps: rg = wid>>1 -> 10 vocab rows, bg = wid&1 -> 64-batch half.
// Lane owns 2 b. acc[q][b] u64 = (even-k, odd-k) partial sums.
__global__ void __launch_bounds__(256) k_logits(
    const float* __restrict__ Wout, const float* __restrict__ bout,
    float* __restrict__ out, int t, int T)
{
    __shared__ __align__(16) float wsm[3][40][64];   // 30KB
    __shared__ float s_cv[4][B_];
    __shared__ int   s_ci[4][B_];

    const int tid = threadIdx.x, bid = blockIdx.x;
    const int lane = tid & 31, wid = tid >> 5;
    const int rg = wid >> 1, bg = wid & 1;
    const int b2 = bg * 64 + lane * 2;
    const int vb = bid * 40;

    const float* h1 = g_h1T[(t + 1) & 1];

    u64 acc[10][2];
    #pragma unroll
    for (int q = 0; q < 10; q++) { acc[q][0] = 0ull; acc[q][1] = 0ull; }

    // staging: 40 rows x 16 units = 640 16B ops; thread does idx = tid, tid+256[, tid+512]
    #define STAGE_LOG(cn) do {                                                \
        int st_ = (cn) - ((cn) / 3) * 3;                                      \
        _Pragma("unroll")                                                     \
        for (int i_ = 0; i_ < 3; i_++) {                                      \
            int idx_ = tid + i_ * 256;                                        \
            if (idx_ < 640) {                                                 \
                int row_ = idx_ >> 4, q_ = (idx_ & 15) * 4;                   \
                cpa16((unsigned)__cvta_generic_to_shared(&wsm[st_][row_][q_]),\
                      Wout + (size_t)(vb + row_) * H_ + (cn) * 64 + q_);      \
            }                                                                 \
        }                                                                     \
    } while (0)

    STAGE_LOG(0); cpcommit();
    STAGE_LOG(1); cpcommit();

    #pragma unroll 1
    for (int c = 0; c < 8; c++) {
        cpwait1();
        __syncthreads();
        const int st = c - (c / 3) * 3;
        const float* xp0 = h1 + (size_t)c * 64 * B_ + b2;
        #pragma unroll 2
        for (int kc = 0; kc < 64; kc += 4) {
            const float* xp = xp0 + (size_t)kc * B_;
            float2 a0 = *(const float2*)(xp);
            float2 a1 = *(const float2*)(xp + B_);
            float2 a2 = *(const float2*)(xp + 2 * B_);
            float2 a3 = *(const float2*)(xp + 3 * B_);
            u64 p0 = pack2(a0.x, a1.x), p1 = pack2(a0.y, a1.y);
            u64 p2 = pack2(a2.x, a3.x), p3 = pack2(a2.y, a3.y);
            #pragma unroll
            for (int q = 0; q < 10; q++) {
                ulonglong2 w = *(const ulonglong2*)&wsm[st][rg * 10 + q][kc];
                fma2(acc[q][0], p0, w.x); fma2(acc[q][1], p1, w.x);
                fma2(acc[q][0], p2, w.y); fma2(acc[q][1], p3, w.y);
            }
        }
        if (c + 2 < 8) STAGE_LOG(c + 2);
        cpcommit();
    }
    #undef STAGE_LOG

    // ---- epilogue: bias, write, per-lane argmax over 10 rows x 2 b ----
    {
        float* op0 = out + ((size_t)(b2 + 0) * T + t) * V_ + vb + rg * 10;
        float* op1 = out + ((size_t)(b2 + 1) * T + t) * V_ + vb + rg * 10;
        float bv0 = -FLT_MAX, bv1 = -FLT_MAX; int bi0 = 0, bi1 = 0;
        #pragma unroll
        for (int q = 0; q < 10; q++) {
            float bq = bout[vb + rg * 10 + q];
            float v0 = hsum2(acc[q][0]) + bq;
            float v1 = hsum2(acc[q][1]) + bq;
            op0[q] = v0;
            op1[q] = v1;
            int col = vb + rg * 10 + q;
            if (v0 > bv0) { bv0 = v0; bi0 = col; }   // first max on ties
            if (v1 > bv1) { bv1 = v1; bi1 = col; }
        }
        s_cv[rg][b2]     = bv0;  s_ci[rg][b2]     = bi0;
        s_cv[rg][b2 + 1] = bv1;  s_ci[rg][b2 + 1] = bi1;
    }
    __syncthreads();
    if (tid < B_) {
        int b = tid;
        float bv = -FLT_MAX; int bi = 0x7fffffff;
        #pragma unroll
        for (int p = 0; p < 4; p++) {
            float v = s_cv[p][b]; int ix = s_ci[p][b];
            if (v > bv || (v == bv && ix < bi)) { bv = v; bi = ix; }
        }
        g_cval[bid * B_ + b] = bv;
        g_cidx[bid * B_ + b] = bi;
    }
}

// ================= final heads =================
__global__ void k_head(const float* __restrict__ Watt, const float* __restrict__ batt,
                       const float* __restrict__ Wsoph, const float* __restrict__ bsoph,
                       float* __restrict__ out, int T)
{
    const float* h1 = g_h1T[T & 1];
    int m = blockIdx.x;          // 0..23
    int b = threadIdx.x;         // 0..127
    size_t base = (size_t)B_ * T * V_;
    const float* w; float bias; float* op;
    if (m < 8) {
        w = Watt + m * H_; bias = batt[m];
        op = out + base + (size_t)b * 8 + m;
    } else {
        int mm = m - 8;
        w = Wsoph + mm * H_; bias = bsoph[mm];
        op = out + base + (size_t)B_ * 8 + (size_t)b * 16 + mm;
    }
    float a = 0.f;
    #pragma unroll 4
    for (int k = 0; k < H_; k += 4) {
        float4 wv = *(const float4*)(w + k);
        a += h1[(k + 0) * B_ + b] * wv.x + h1[(k + 1) * B_ + b] * wv.y
           + h1[(k + 2) * B_ + b] * wv.z + h1[(k + 3) * B_ + b] * wv.w;
    }
    *op = a + bias;
}

// ================= launch =================
extern "C" void kernel_launch(void* const* d_in, const int* in_sizes, int n_in,
                              void* d_out, int out_size)
{
    const float* noise = (const float*)d_in[0];
    const float* emb   = (const float*)d_in[1];
    const float* Wih0  = (const float*)d_in[2];
    const float* Whh0  = (const float*)d_in[3];
    const float* bih0  = (const float*)d_in[4];
    const float* bhh0  = (const float*)d_in[5];
    const float* Wih1  = (const float*)d_in[6];
    const float* Whh1  = (const float*)d_in[7];
    const float* bih1  = (const float*)d_in[8];
    const float* bhh1  = (const float*)d_in[9];
    const float* Wout  = (const float*)d_in[10];
    const float* bout  = (const float*)d_in[11];
    const float* Watt  = (const float*)d_in[12];
    const float* batt  = (const float*)d_in[13];
    const float* Wsoph = (const float*)d_in[14];
    const float* bsoph = (const float*)d_in[15];
    float* out = (float*)d_out;

    int T = (out_size - B_ * 24) / (B_ * V_);
    if (T <= 0) T = 200;

    k_init<<<256, 256>>>(noise);
    for (int t = 0; t < T; t++) {
        k_lstm<0><<<128, 256>>>(emb, Wih0, Whh0, bih0, bhh0, t);
        k_lstm<1><<<128, 256>>>(emb, Wih1, Whh1, bih1, bhh1, t);
        k_logits<<<125, 256>>>(Wout, bout, out, t, T);
    }
    k_head<<<24, 128>>>(Watt, batt, Wsoph, bsoph, out, T);
}

// round 13
// speedup vs baseline: 1.5222x; 1.5222x over previous
#include <cuda_runtime.h>
#include <math.h>
#include <float.h>

#define B_   128
#define H_   512
#define E_   256
#define ND_  128
#define V_   5000
#define K0_  384      // E_ + ND_

typedef unsigned long long u64;

// ---------------- persistent device state ----------------
__device__ __align__(16) float g_h0T[2][H_ * B_];   // [k][b], ping-pong
__device__ __align__(16) float g_h1T[2][H_ * B_];
__device__ __align__(16) float g_h1R[B_ * H_];      // h1 row-major [b][k] (for logits staging)
__device__ __align__(16) float g_c0[H_ * B_];       // cell state [j][b]
__device__ __align__(16) float g_c1[H_ * B_];
__device__ __align__(16) float g_xnT[ND_ * B_];     // noise transposed [k][b] (static)
__device__ __align__(16) float g_cval[125 * B_];    // [p][b]
__device__ int   g_cidx[125 * B_];

__device__ __forceinline__ float sigmf(float x) { return 1.0f / (1.0f + expf(-x)); }

__device__ __forceinline__ u64 dup2(float a) {
    u64 r; asm("mov.b64 %0,{%1,%1};" : "=l"(r) : "f"(a)); return r;
}
__device__ __forceinline__ u64 pack2(float lo, float hi) {
    u64 r; asm("mov.b64 %0,{%1,%2};" : "=l"(r) : "f"(lo), "f"(hi)); return r;
}
__device__ __forceinline__ void fma2(u64& d, u64 x, u64 w) {
    asm("fma.rn.f32x2 %0,%1,%2,%0;" : "+l"(d) : "l"(x), "l"(w));
}
__device__ __forceinline__ u64 add2(u64 a, u64 b) {
    u64 r; asm("add.rn.f32x2 %0,%1,%2;" : "=l"(r) : "l"(a), "l"(b)); return r;
}
__device__ __forceinline__ void unpack2(u64 a, float& x, float& y) {
    asm("mov.b64 {%0,%1},%2;" : "=f"(x), "=f"(y) : "l"(a));
}
__device__ __forceinline__ float hsum2(u64 a) {
    float x, y; unpack2(a, x, y); return x + y;
}
__device__ __forceinline__ void cpa16(unsigned s, const void* g) {
    asm volatile("cp.async.cg.shared.global [%0], [%1], 16;" :: "r"(s), "l"(g));
}
__device__ __forceinline__ void cpcommit() { asm volatile("cp.async.commit_group;"); }
__device__ __forceinline__ void cpwait1()  { asm volatile("cp.async.wait_group 1;"); }

// ================= init =================
__global__ void k_init(const float* __restrict__ noise) {
    int i = blockIdx.x * 256 + threadIdx.x;
    if (i < H_ * B_) {
        g_h0T[0][i] = 0.f; g_h1T[0][i] = 0.f;
        g_c0[i] = 0.f;     g_c1[i] = 0.f;
    }
    if (i < ND_ * B_) {
        int k = i >> 7, b = i & 127;
        g_xnT[k * B_ + b] = noise[b * ND_ + k];
    }
}

// ================= LSTM kernels (R7 proven) =================
// grid 128, block 512 = 16 warps = 8 kz x 2 rw. Warp: 8 rows (4 gates x 2 j) x 128 batch.
template<int LAYER>
__device__ __forceinline__ void lstm_body(
    const float* __restrict__ Wih, const float* __restrict__ Whh,
    const float* __restrict__ bih, const float* __restrict__ bhh,
    const float* __restrict__ emb,
    const float* __restrict__ xin,
    const float* __restrict__ hrd,
    float* __restrict__ hwr,
    float* __restrict__ cst,
    int t)
{
    constexpr int KIH  = (LAYER == 0) ? K0_ : H_;
    constexpr int SLEN1 = KIH / 8;
    __shared__ __align__(16) u64 sred[8][32][16];
    __shared__ int s_tok[B_];

    const int tid = threadIdx.x, bid = blockIdx.x;
    const int lane = tid & 31, wid = tid >> 5;
    const int kz = wid >> 1, rw = wid & 1;
    const int lane4 = lane * 4;
    const int jbase = bid * 4 + rw * 2;

    if (LAYER == 0) {
        if (tid < B_) {
            int tok = 1;
            if (t > 0) {
                float bv = -FLT_MAX; int bi = 0x7fffffff;
                #pragma unroll 5
                for (int p = 0; p < 125; p++) {
                    float v = g_cval[p * B_ + tid];
                    int  ix = g_cidx[p * B_ + tid];
                    if (v > bv || (v == bv && ix < bi)) { bv = v; bi = ix; }
                }
                tok = bi;
            }
            s_tok[tid] = tok;
        }
        __syncthreads();
    }

    u64 acc[16];
    #pragma unroll
    for (int a = 0; a < 16; a++) acc[a] = 0ull;

#define FMA8(WB, KK)                                                        \
    _Pragma("unroll")                                                       \
    for (int g = 0; g < 4; g++) {                                           \
        _Pragma("unroll")                                                   \
        for (int jj = 0; jj < 2; jj++) {                                    \
            int r = g * 2 + jj;                                             \
            float4 wv = *(const float4*)((WB) + (size_t)(g * H_ + jj) * KIH + (KK)); \
            u64 wa = dup2(wv.x), wb = dup2(wv.y), wc = dup2(wv.z), wd = dup2(wv.w);  \
            fma2(acc[r*2], xq0.x, wa); fma2(acc[r*2+1], xq0.y, wa);         \
            fma2(acc[r*2], xq1.x, wb); fma2(acc[r*2+1], xq1.y, wb);         \
            fma2(acc[r*2], xq2.x, wc); fma2(acc[r*2+1], xq2.y, wc);         \
            fma2(acc[r*2], xq3.x, wd); fma2(acc[r*2+1], xq3.y, wd);         \
        }                                                                   \
    }

    {
        const float* wbase = Wih + (size_t)jbase * KIH;
        if (LAYER == 0) {
            const float* e0 = emb + (size_t)s_tok[lane4 + 0] * E_;
            const float* e1 = emb + (size_t)s_tok[lane4 + 1] * E_;
            const float* e2 = emb + (size_t)s_tok[lane4 + 2] * E_;
            const float* e3 = emb + (size_t)s_tok[lane4 + 3] * E_;
            const int k0 = kz * SLEN1;
            #pragma unroll
            for (int ko = 0; ko < SLEN1; ko += 4) {
                const int k = k0 + ko;
                ulonglong2 xq0, xq1, xq2, xq3;
                if (k < E_) {
                    float4 f0 = *(const float4*)(e0 + k);
                    float4 f1 = *(const float4*)(e1 + k);
                    float4 f2 = *(const float4*)(e2 + k);
                    float4 f3 = *(const float4*)(e3 + k);
                    xq0.x = pack2(f0.x, f1.x); xq0.y = pack2(f2.x, f3.x);
                    xq1.x = pack2(f0.y, f1.y); xq1.y = pack2(f2.y, f3.y);
                    xq2.x = pack2(f0.z, f1.z); xq2.y = pack2(f2.z, f3.z);
                    xq3.x = pack2(f0.w, f1.w); xq3.y = pack2(f2.w, f3.w);
                } else {
                    const float* nb = g_xnT + (size_t)(k - E_) * B_ + lane4;
                    xq0 = *(const ulonglong2*)(nb + 0 * B_);
                    xq1 = *(const ulonglong2*)(nb + 1 * B_);
                    xq2 = *(const ulonglong2*)(nb + 2 * B_);
                    xq3 = *(const ulonglong2*)(nb + 3 * B_);
                }
                FMA8(wbase, k);
            }
        } else {
            const int k0 = kz * SLEN1;
            #pragma unroll 4
            for (int k = k0; k < k0 + SLEN1; k += 4) {
                ulonglong2 xq0 = *(const ulonglong2*)(xin + (size_t)(k + 0) * B_ + lane4);
                ulonglong2 xq1 = *(const ulonglong2*)(xin + (size_t)(k + 1) * B_ + lane4);
                ulonglong2 xq2 = *(const ulonglong2*)(xin + (size_t)(k + 2) * B_ + lane4);
                ulonglong2 xq3 = *(const ulonglong2*)(xin + (size_t)(k + 3) * B_ + lane4);
                FMA8(wbase, k);
            }
        }
    }

    {
        const float* wbase2 = Whh + (size_t)jbase * H_;
        const int k0 = kz * (H_ / 8);
        #pragma unroll 4
        for (int k = k0; k < k0 + H_ / 8; k += 4) {
            ulonglong2 xq0 = *(const ulonglong2*)(hrd + (size_t)(k + 0) * B_ + lane4);
            ulonglong2 xq1 = *(const ulonglong2*)(hrd + (size_t)(k + 1) * B_ + lane4);
            ulonglong2 xq2 = *(const ulonglong2*)(hrd + (size_t)(k + 2) * B_ + lane4);
            ulonglong2 xq3 = *(const ulonglong2*)(hrd + (size_t)(k + 3) * B_ + lane4);
            #pragma unroll
            for (int g = 0; g < 4; g++) {
                #pragma unroll
                for (int jj = 0; jj < 2; jj++) {
                    int r = g * 2 + jj;
                    float4 wv = *(const float4*)(wbase2 + (size_t)(g * H_ + jj) * H_ + k);
                    u64 wa = dup2(wv.x), wb = dup2(wv.y), wc = dup2(wv.z), wd = dup2(wv.w);
                    fma2(acc[r*2], xq0.x, wa); fma2(acc[r*2+1], xq0.y, wa);
                    fma2(acc[r*2], xq1.x, wb); fma2(acc[r*2+1], xq1.y, wb);
                    fma2(acc[r*2], xq2.x, wc); fma2(acc[r*2+1], xq2.y, wc);
                    fma2(acc[r*2], xq3.x, wd); fma2(acc[r*2+1], xq3.y, wd);
                }
            }
        }
    }
#undef FMA8

    if (kz >= 4) {
        #pragma unroll
        for (int a = 0; a < 16; a++) sred[(kz - 4) * 2 + rw][lane][a] = acc[a];
    }
    __syncthreads();
    if (kz < 4) {
        #pragma unroll
        for (int a = 0; a < 16; a++) acc[a] = add2(acc[a], sred[kz * 2 + rw][lane][a]);
    }
    __syncthreads();
    if (kz >= 1 && kz < 4) {
        #pragma unroll
        for (int a = 0; a < 16; a++) sred[(kz - 1) * 2 + rw][lane][a] = acc[a];
    }
    __syncthreads();
    if (kz == 0) {
        #pragma unroll
        for (int s = 0; s < 3; s++)
            #pragma unroll
            for (int a = 0; a < 16; a++)
                acc[a] = add2(acc[a], sred[s * 2 + rw][lane][a]);

        #pragma unroll
        for (int jj = 0; jj < 2; jj++) {
            int j = jbase + jj;
            float gv[4][4];
            #pragma unroll
            for (int g = 0; g < 4; g++) {
                unpack2(acc[(g*2+jj)*2 + 0], gv[g][0], gv[g][1]);
                unpack2(acc[(g*2+jj)*2 + 1], gv[g][2], gv[g][3]);
            }
            float bsum[4];
            #pragma unroll
            for (int g = 0; g < 4; g++) bsum[g] = bih[g * H_ + j] + bhh[g * H_ + j];
            float4 c4 = *(float4*)&cst[j * B_ + lane4];
            float cc[4] = {c4.x, c4.y, c4.z, c4.w};
            float hh[4];
            #pragma unroll
            for (int i = 0; i < 4; i++) {
                float iv = sigmf(gv[0][i] + bsum[0]);
                float fv = sigmf(gv[1][i] + bsum[1]);
                float gg = tanhf(gv[2][i] + bsum[2]);
                float ov = sigmf(gv[3][i] + bsum[3]);
                float cn = fv * cc[i] + iv * gg;
                cc[i] = cn;
                hh[i] = ov * tanhf(cn);
            }
            *(float4*)&cst[j * B_ + lane4] = make_float4(cc[0], cc[1], cc[2], cc[3]);
            *(float4*)&hwr[j * B_ + lane4] = make_float4(hh[0], hh[1], hh[2], hh[3]);
            if (LAYER == 1) {
                #pragma unroll
                for (int i = 0; i < 4; i++)
                    g_h1R[(size_t)(lane4 + i) * H_ + j] = hh[i];
            }
        }
    }
}

__global__ void __launch_bounds__(512) k_lstm0(
    const float* __restrict__ emb,
    const float* __restrict__ Wih, const float* __restrict__ Whh,
    const float* __restrict__ bih, const float* __restrict__ bhh, int t)
{
    lstm_body<0>(Wih, Whh, bih, bhh, emb, nullptr,
                 g_h0T[t & 1], g_h0T[(t + 1) & 1], g_c0, t);
}

__global__ void __launch_bounds__(512) k_lstm1(
    const float* __restrict__ Wih, const float* __restrict__ Whh,
    const float* __restrict__ bih, const float* __restrict__ bhh, int t)
{
    lstm_body<1>(Wih, Whh, bih, bhh, nullptr, g_h0T[(t + 1) & 1],
                 g_h1T[t & 1], g_h1T[(t + 1) & 1], g_c1, t);
}

// ================= logits + partial argmax (smem-x, K-paired, swizzled) =================
// grid 125, block 512 = 16 warps = 8 rowg x 2 bg. Warp: 5 vocab rows x 64 batch, lane = 2 b.
// acc[q][i] u64 = (even-k, odd-k) sums for (row cbase+q, b2+i).
// x staged from g_h1R [b][k] in 32-k chunks, cp.async double-buffered,
// swizzle: quad u of row b stored at quad (u ^ ((b>>1)&7)) -> conflict-free LDS.128.
__global__ void __launch_bounds__(512) k_logits(
    const float* __restrict__ Wout, const float* __restrict__ bout,
    float* __restrict__ out, int t, int T)
{
    __shared__ __align__(16) float xs[2][128 * 32];   // 32KB
    __shared__ float s_cv[8][B_];
    __shared__ int   s_ci[8][B_];

    const int tid = threadIdx.x, bid = blockIdx.x;
    const int lane = tid & 31, wid = tid >> 5;
    const int rowg = wid >> 1, bg = wid & 1;
    const int b2 = bg * 64 + lane * 2;
    const int cbase = bid * 40 + rowg * 5;
    const int key = lane & 7;                 // == (b2>>1)&7 == ((b2+1)>>1)&7

    const float* h1r = g_h1R;
    const float* wp0 = Wout + (size_t)(cbase + 0) * H_;
    const float* wp1 = Wout + (size_t)(cbase + 1) * H_;
    const float* wp2 = Wout + (size_t)(cbase + 2) * H_;
    const float* wp3 = Wout + (size_t)(cbase + 3) * H_;
    const float* wp4 = Wout + (size_t)(cbase + 4) * H_;

    // staging: 1024 16B units per chunk, 2 per thread
    int sb0 = (tid * 2) >> 3,       su0 = (tid * 2) & 7;        // unit 2*tid
    int sb1 = (tid * 2 + 1) >> 3,   su1 = (tid * 2 + 1) & 7;    // unit 2*tid+1
    unsigned d0[2], d1[2];
    #pragma unroll
    for (int bf = 0; bf < 2; bf++) {
        d0[bf] = (unsigned)__cvta_generic_to_shared(
            &xs[bf][sb0 * 32 + ((su0 ^ ((sb0 >> 1) & 7)) << 2)]);
        d1[bf] = (unsigned)__cvta_generic_to_shared(
            &xs[bf][sb1 * 32 + ((su1 ^ ((sb1 >> 1) & 7)) << 2)]);
    }
    const float* s0 = h1r + (size_t)sb0 * H_ + su0 * 4;
    const float* s1 = h1r + (size_t)sb1 * H_ + su1 * 4;

    u64 acc[5][2];
    #pragma unroll
    for (int q = 0; q < 5; q++) { acc[q][0] = 0ull; acc[q][1] = 0ull; }

    cpa16(d0[0], s0);          cpa16(d1[0], s1);          cpcommit();
    cpa16(d0[1], s0 + 32);     cpa16(d1[1], s1 + 32);     cpcommit();

    #pragma unroll 1
    for (int c = 0; c < 16; c++) {
        cpwait1();
        __syncthreads();
        const float* xbuf = xs[c & 1];
        const float* xa0 = xbuf + (size_t)b2 * 32;
        const float* xb0 = xbuf + (size_t)(b2 + 1) * 32;
        const int koff = c * 32;

        #pragma unroll 4
        for (int kc = 0; kc < 32; kc += 4) {
            const int sq = ((kc >> 2) ^ key) << 2;
            ulonglong2 xa = *(const ulonglong2*)(xa0 + sq);
            ulonglong2 xb = *(const ulonglong2*)(xb0 + sq);
            ulonglong2 w;
            w = *(const ulonglong2*)(wp0 + koff + kc);
            fma2(acc[0][0], xa.x, w.x); fma2(acc[0][0], xa.y, w.y);
            fma2(acc[0][1], xb.x, w.x); fma2(acc[0][1], xb.y, w.y);
            w = *(const ulonglong2*)(wp1 + koff + kc);
            fma2(acc[1][0], xa.x, w.x); fma2(acc[1][0], xa.y, w.y);
            fma2(acc[1][1], xb.x, w.x); fma2(acc[1][1], xb.y, w.y);
            w = *(const ulonglong2*)(wp2 + koff + kc);
            fma2(acc[2][0], xa.x, w.x); fma2(acc[2][0], xa.y, w.y);
            fma2(acc[2][1], xb.x, w.x); fma2(acc[2][1], xb.y, w.y);
            w = *(const ulonglong2*)(wp3 + koff + kc);
            fma2(acc[3][0], xa.x, w.x); fma2(acc[3][0], xa.y, w.y);
            fma2(acc[3][1], xb.x, w.x); fma2(acc[3][1], xb.y, w.y);
            w = *(const ulonglong2*)(wp4 + koff + kc);
            fma2(acc[4][0], xa.x, w.x); fma2(acc[4][0], xa.y, w.y);
            fma2(acc[4][1], xb.x, w.x); fma2(acc[4][1], xb.y, w.y);
        }
        __syncthreads();
        if (c + 2 < 16) {
            int bf = c & 1;   // (c+2)&1
            cpa16(d0[bf], s0 + (c + 2) * 32);
            cpa16(d1[bf], s1 + (c + 2) * 32);
        }
        cpcommit();
    }

    // ---- epilogue: bias, write, per-lane argmax over 5 rows x 2 b ----
    {
        float* op0 = out + ((size_t)(b2 + 0) * T + t) * V_ + cbase;
        float* op1 = out + ((size_t)(b2 + 1) * T + t) * V_ + cbase;
        float bv0 = -FLT_MAX, bv1 = -FLT_MAX; int bi0 = 0, bi1 = 0;
        #pragma unroll
        for (int q = 0; q < 5; q++) {
            float bq = bout[cbase + q];
            float v0 = hsum2(acc[q][0]) + bq;
            float v1 = hsum2(acc[q][1]) + bq;
            op0[q] = v0;
            op1[q] = v1;
            int col = cbase + q;
            if (v0 > bv0) { bv0 = v0; bi0 = col; }   // first max on ties
            if (v1 > bv1) { bv1 = v1; bi1 = col; }
        }
        s_cv[rowg][b2]     = bv0;  s_ci[rowg][b2]     = bi0;
        s_cv[rowg][b2 + 1] = bv1;  s_ci[rowg][b2 + 1] = bi1;
    }
    __syncthreads();
    if (tid < B_) {
        int b = tid;
        float bv = -FLT_MAX; int bi = 0x7fffffff;
        #pragma unroll
        for (int p = 0; p < 8; p++) {
            float v = s_cv[p][b]; int ix = s_ci[p][b];
            if (v > bv || (v == bv && ix < bi)) { bv = v; bi = ix; }
        }
        g_cval[bid * B_ + b] = bv;
        g_cidx[bid * B_ + b] = bi;
    }
}

// ================= final heads =================
__global__ void k_head(const float* __restrict__ Watt, const float* __restrict__ batt,
                       const float* __restrict__ Wsoph, const float* __restrict__ bsoph,
                       float* __restrict__ out, int T)
{
    const float* h1 = g_h1T[T & 1];
    int m = blockIdx.x;          // 0..23
    int b = threadIdx.x;         // 0..127
    size_t base = (size_t)B_ * T * V_;
    const float* w; float bias; float* op;
    if (m < 8) {
        w = Watt + m * H_; bias = batt[m];
        op = out + base + (size_t)b * 8 + m;
    } else {
        int mm = m - 8;
        w = Wsoph + mm * H_; bias = bsoph[mm];
        op = out + base + (size_t)B_ * 8 + (size_t)b * 16 + mm;
    }
    float a = 0.f;
    #pragma unroll 4
    for (int k = 0; k < H_; k += 4) {
        float4 wv = *(const float4*)(w + k);
        a += h1[(k + 0) * B_ + b] * wv.x + h1[(k + 1) * B_ + b] * wv.y
           + h1[(k + 2) * B_ + b] * wv.z + h1[(k + 3) * B_ + b] * wv.w;
    }
    *op = a + bias;
}

// ================= launch =================
extern "C" void kernel_launch(void* const* d_in, const int* in_sizes, int n_in,
                              void* d_out, int out_size)
{
    const float* noise = (const float*)d_in[0];
    const float* emb   = (const float*)d_in[1];
    const float* Wih0  = (const float*)d_in[2];
    const float* Whh0  = (const float*)d_in[3];
    const float* bih0  = (const float*)d_in[4];
    const float* bhh0  = (const float*)d_in[5];
    const float* Wih1  = (const float*)d_in[6];
    const float* Whh1  = (const float*)d_in[7];
    const float* bih1  = (const float*)d_in[8];
    const float* bhh1  = (const float*)d_in[9];
    const float* Wout  = (const float*)d_in[10];
    const float* bout  = (const float*)d_in[11];
    const float* Watt  = (const float*)d_in[12];
    const float* batt  = (const float*)d_in[13];
    const float* Wsoph = (const float*)d_in[14];
    const float* bsoph = (const float*)d_in[15];
    float* out = (float*)d_out;

    int T = (out_size - B_ * 24) / (B_ * V_);
    if (T <= 0) T = 200;

    k_init<<<256, 256>>>(noise);
    for (int t = 0; t < T; t++) {
        k_lstm0<<<128, 512>>>(emb, Wih0, Whh0, bih0, bhh0, t);
        k_lstm1<<<128, 512>>>(Wih1, Whh1, bih1, bhh1, t);
        k_logits<<<125, 512>>>(Wout, bout, out, t, T);
    }
    k_head<<<24, 128>>>(Watt, batt, Wsoph, bsoph, out, T);
}